// round 4
// baseline (speedup 1.0000x reference)
#include <cuda_runtime.h>
#include <cuda_bf16.h>

// GaussianConditionalStanh: fused quantize(symbols) + dequantize.
//   y = inputs - means
//   idx = searchsorted(mid, y), side='left', mid = 0.5*(c[l]+c[l+1])
//   out[0:N]  = (float)idx
//   out[N:2N] = codebook[idx] + means
//
// R2: affine guess + exact fixup (codebook near-uniform -> <=1 fixup iter,
// but loops guarantee exactness for ANY sorted codebook). 2x float4 per
// thread for MLP. Streaming cache hints (no reuse).

#define L_CODE 60
#define NMID   59

__device__ __forceinline__ int nearest_idx(float y, const float* __restrict__ smid,
                                           float m_lo, float inv_step)
{
    // Affine guess of count{ k : smid[k] < y }
    float gf = (y - m_lo) * inv_step;
    int g = (int)gf;                       // trunc toward zero
    g = max(0, min(g, NMID));
    // Exact fixup (sorted array): terminate with smid[g-1] < y <= smid[g]
    while (g < NMID && smid[g] < y) ++g;
    while (g > 0 && smid[g - 1] >= y) --g;
    return g;
}

__global__ __launch_bounds__(256)
void gcs_kernel(const float4* __restrict__ x4,
                const float4* __restrict__ m4,
                const float*  __restrict__ codebook,
                float4* __restrict__ sym4,
                float4* __restrict__ dq4,
                int n4)
{
    __shared__ float sc[L_CODE];
    __shared__ float smid[NMID + 1];

    if (threadIdx.x < L_CODE)
        sc[threadIdx.x] = codebook[threadIdx.x];
    __syncthreads();
    if (threadIdx.x < NMID)
        smid[threadIdx.x] = 0.5f * (sc[threadIdx.x] + sc[threadIdx.x + 1]);

    // Affine model params from codebook ends (sc valid after first sync)
    float m_lo = 0.5f * (sc[0] + sc[1]);
    float m_hi = 0.5f * (sc[NMID - 1] + sc[NMID]);
    float inv_step = (float)(NMID - 1) / (m_hi - m_lo);
    __syncthreads();

    int i = blockIdx.x * (blockDim.x * 2) + threadIdx.x;
    int j = i + blockDim.x;

    if (j < n4) {
        // Batch 4 independent 128b loads up front (MLP)
        float4 xa = __ldcs(&x4[i]);
        float4 xb = __ldcs(&x4[j]);
        float4 ma = __ldcs(&m4[i]);
        float4 mb = __ldcs(&m4[j]);

        int a0 = nearest_idx(xa.x - ma.x, smid, m_lo, inv_step);
        int a1 = nearest_idx(xa.y - ma.y, smid, m_lo, inv_step);
        int a2 = nearest_idx(xa.z - ma.z, smid, m_lo, inv_step);
        int a3 = nearest_idx(xa.w - ma.w, smid, m_lo, inv_step);
        int b0 = nearest_idx(xb.x - mb.x, smid, m_lo, inv_step);
        int b1 = nearest_idx(xb.y - mb.y, smid, m_lo, inv_step);
        int b2 = nearest_idx(xb.z - mb.z, smid, m_lo, inv_step);
        int b3 = nearest_idx(xb.w - mb.w, smid, m_lo, inv_step);

        float4 sa = make_float4((float)a0, (float)a1, (float)a2, (float)a3);
        float4 sb = make_float4((float)b0, (float)b1, (float)b2, (float)b3);
        float4 da = make_float4(sc[a0] + ma.x, sc[a1] + ma.y,
                                sc[a2] + ma.z, sc[a3] + ma.w);
        float4 db = make_float4(sc[b0] + mb.x, sc[b1] + mb.y,
                                sc[b2] + mb.z, sc[b3] + mb.w);

        __stcs(&sym4[i], sa);
        __stcs(&sym4[j], sb);
        __stcs(&dq4[i], da);
        __stcs(&dq4[j], db);
    } else {
        // Tail (not hit for the bench shape, kept for generality)
        for (int k = i; k < n4; k += blockDim.x) {
            float4 xv = __ldcs(&x4[k]);
            float4 mv = __ldcs(&m4[k]);
            int i0 = nearest_idx(xv.x - mv.x, smid, m_lo, inv_step);
            int i1 = nearest_idx(xv.y - mv.y, smid, m_lo, inv_step);
            int i2 = nearest_idx(xv.z - mv.z, smid, m_lo, inv_step);
            int i3 = nearest_idx(xv.w - mv.w, smid, m_lo, inv_step);
            float4 sv = make_float4((float)i0, (float)i1, (float)i2, (float)i3);
            float4 dv = make_float4(sc[i0] + mv.x, sc[i1] + mv.y,
                                    sc[i2] + mv.z, sc[i3] + mv.w);
            __stcs(&sym4[k], sv);
            __stcs(&dq4[k], dv);
        }
    }
}

extern "C" void kernel_launch(void* const* d_in, const int* in_sizes, int n_in,
                              void* d_out, int out_size)
{
    const float* inputs   = (const float*)d_in[0];
    const float* means    = (const float*)d_in[1];
    const float* codebook = (const float*)d_in[2];
    float* out = (float*)d_out;

    int n  = in_sizes[0];      // 28,311,552
    int n4 = n / 4;            // 7,077,888

    float* sym = out;
    float* dq  = out + n;

    const int threads = 256;
    const int per_block = threads * 2;          // 2 float4 per thread
    int blocks = (n4 + per_block - 1) / per_block;   // 13824 exact

    gcs_kernel<<<blocks, threads>>>(
        (const float4*)inputs, (const float4*)means, codebook,
        (float4*)sym, (float4*)dq, n4);
}

// round 5
// speedup vs baseline: 1.2640x; 1.2640x over previous
#include <cuda_runtime.h>
#include <cuda_bf16.h>
#include <math_constants.h>

// GaussianConditionalStanh: fused quantize(symbols) + dequantize.
//   y = inputs - means
//   idx = searchsorted(mid, y), side='left'  (count of mid < y)
//   out[0:N]  = (float)idx
//   out[N:2N] = codebook[idx] + means
//
// R4: affine guess + FIXED 2-probe branchless correction.
//   If |u_k - k| < 1 for all midpoints (verified at runtime per block),
//   then idx = g0 + [mid[g0]<y] + [mid[g0+1]<y], g0 = clamp(floor(u),0,58).
//   Otherwise: uniform-branch fallback to branchless binary search (exact
//   for any sorted codebook).

#define L_CODE 60
#define NMID   59

__global__ __launch_bounds__(256)
void gcs_kernel(const float4* __restrict__ x4,
                const float4* __restrict__ m4,
                const float*  __restrict__ codebook,
                float4* __restrict__ sym4,
                float4* __restrict__ dq4,
                int n4)
{
    __shared__ float sc[L_CODE];       // codebook values
    __shared__ float smid[NMID + 1];   // midpoints, smid[59] = +INF sentinel
    __shared__ int   sBad;             // affine-model violation flag

    if (threadIdx.x == 0) sBad = 0;
    if (threadIdx.x < L_CODE)
        sc[threadIdx.x] = codebook[threadIdx.x];
    __syncthreads();
    if (threadIdx.x < NMID)
        smid[threadIdx.x] = 0.5f * (sc[threadIdx.x] + sc[threadIdx.x + 1]);
    if (threadIdx.x == NMID)
        smid[NMID] = CUDART_INF_F;
    __syncthreads();

    const float m_lo = smid[0];
    const float inv_step = (float)(NMID - 1) / (smid[NMID - 1] - m_lo);

    // Runtime exactness check: |u_k - k| < 1 for all k (margin 0.998).
    if (threadIdx.x < NMID) {
        float u = (smid[threadIdx.x] - m_lo) * inv_step;
        if (fabsf(u - (float)threadIdx.x) > 0.998f) sBad = 1;
    }
    __syncthreads();
    const bool fast = (sBad == 0);

    int i = blockIdx.x * blockDim.x + threadIdx.x;
    int stride = gridDim.x * blockDim.x;

    for (; i < n4; i += stride) {
        float4 xv = x4[i];
        float4 mv = m4[i];

        float y0 = xv.x - mv.x;
        float y1 = xv.y - mv.y;
        float y2 = xv.z - mv.z;
        float y3 = xv.w - mv.w;

        int i0, i1, i2, i3;
        if (fast) {
            // g0 = clamp(floor(u), 0, 58); idx = g0 + (mid[g0]<y) + (mid[g0+1]<y)
            int g0 = min(max((int)floorf((y0 - m_lo) * inv_step), 0), NMID - 1);
            int g1 = min(max((int)floorf((y1 - m_lo) * inv_step), 0), NMID - 1);
            int g2 = min(max((int)floorf((y2 - m_lo) * inv_step), 0), NMID - 1);
            int g3 = min(max((int)floorf((y3 - m_lo) * inv_step), 0), NMID - 1);
            i0 = g0 + (smid[g0] < y0) + (smid[g0 + 1] < y0);
            i1 = g1 + (smid[g1] < y1) + (smid[g1 + 1] < y1);
            i2 = g2 + (smid[g2] < y2) + (smid[g2 + 1] < y2);
            i3 = g3 + (smid[g3] < y3) + (smid[g3 + 1] < y3);
        } else {
            // Exact branchless binary search fallback (any sorted codebook).
            i0 = 0; i1 = 0; i2 = 0; i3 = 0;
            #pragma unroll
            for (int step = 32; step > 0; step >>= 1) {
                int n0 = i0 + step; if (n0 <= NMID && smid[n0 - 1] < y0) i0 = n0;
                int n1 = i1 + step; if (n1 <= NMID && smid[n1 - 1] < y1) i1 = n1;
                int n2 = i2 + step; if (n2 <= NMID && smid[n2 - 1] < y2) i2 = n2;
                int n3 = i3 + step; if (n3 <= NMID && smid[n3 - 1] < y3) i3 = n3;
            }
        }

        float4 sv = make_float4((float)i0, (float)i1, (float)i2, (float)i3);
        float4 dv = make_float4(sc[i0] + mv.x, sc[i1] + mv.y,
                                sc[i2] + mv.z, sc[i3] + mv.w);
        sym4[i] = sv;
        dq4[i] = dv;
    }
}

extern "C" void kernel_launch(void* const* d_in, const int* in_sizes, int n_in,
                              void* d_out, int out_size)
{
    const float* inputs   = (const float*)d_in[0];
    const float* means    = (const float*)d_in[1];
    const float* codebook = (const float*)d_in[2];
    float* out = (float*)d_out;

    int n  = in_sizes[0];      // 28,311,552
    int n4 = n / 4;            // 7,077,888

    float* sym = out;
    float* dq  = out + n;

    const int threads = 256;
    int blocks = (n4 + threads - 1) / threads;   // 27648 exact

    gcs_kernel<<<blocks, threads>>>(
        (const float4*)inputs, (const float4*)means, codebook,
        (float4*)sym, (float4*)dq, n4);
}